// round 6
// baseline (speedup 1.0000x reference)
#include <cuda_runtime.h>

// ---------------------------------------------------------------------------
// GCN 4-layer forward on GB300 (sm_103a).
// R5: R2 execution structure + new fma-bound f32x2 GEMM:
//   W staged duplicated (w,w), X staged row-pair packed (r0,r1) -> zero movs,
//   thread = 4 cols x 8 rows, warp interleaves 8 cg x 4 rg for LDS dedup.
// ---------------------------------------------------------------------------

#define MAX_N 100000
#define MAX_E 800000
#define MAX_G 500

__device__ float g_norm_out[MAX_N];
__device__ float g_norm_in[MAX_N];
__device__ int   g_deg_out[MAX_N];
__device__ int   g_deg_in[MAX_N];
__device__ int   g_row_ptr[MAX_N + 1];
__device__ int   g_cursor[MAX_N];
__device__ int   g_csr_src[MAX_E];
__device__ float g_h0[MAX_N * 128];
__device__ float g_h1[MAX_N * 64];
__device__ float g_gsum[MAX_G * 4];
__device__ int   g_gcnt[MAX_G];
__device__ int   g_bsum[128];
__device__ int   g_boff[128];

typedef unsigned long long ull;

__device__ __forceinline__ ull pk(float lo, float hi) {
    ull r; asm("mov.b64 %0, {%1,%2};" : "=l"(r) : "f"(lo), "f"(hi)); return r;
}
__device__ __forceinline__ void fma2(ull& d, ull a, ull b) {
    asm("fma.rn.f32x2 %0, %1, %2, %0;" : "+l"(d) : "l"(a), "l"(b));
}
__device__ __forceinline__ float2 upk(ull v) {
    float2 f; asm("mov.b64 {%0,%1}, %2;" : "=f"(f.x), "=f"(f.y) : "l"(v)); return f;
}

// ---------------------------------------------------------------------------
// Preprocessing
// ---------------------------------------------------------------------------
__global__ void zero_kernel(int n, int g) {
    int i = blockIdx.x * blockDim.x + threadIdx.x;
    if (i < n) { g_deg_out[i] = 0; g_deg_in[i] = 0; }
    if (i < g * 4) g_gsum[i] = 0.0f;
    if (i < g) g_gcnt[i] = 0;
}

__global__ void degree_kernel(const int* __restrict__ src,
                              const int* __restrict__ dst, int e) {
    int i = blockIdx.x * blockDim.x + threadIdx.x;
    if (i < e) {
        atomicAdd(&g_deg_out[src[i]], 1);
        atomicAdd(&g_deg_in[dst[i]], 1);
    }
}

__global__ void scan_pass1(int n) {
    __shared__ int sw[8];
    int b = blockIdx.x, t = threadIdx.x;
    int i0 = b * 1024 + t * 4;
    int s = 0;
    #pragma unroll
    for (int j = 0; j < 4; j++) {
        int i = i0 + j;
        if (i < n) {
            int di = g_deg_in[i];
            s += di;
            g_norm_in[i]  = rsqrtf(fmaxf((float)di, 1.0f));
            g_norm_out[i] = rsqrtf(fmaxf((float)g_deg_out[i], 1.0f));
        }
    }
    #pragma unroll
    for (int o = 16; o; o >>= 1) s += __shfl_down_sync(0xffffffffu, s, o);
    if ((t & 31) == 0) sw[t >> 5] = s;
    __syncthreads();
    if (t < 8) {
        s = sw[t];
        #pragma unroll
        for (int o = 4; o; o >>= 1) s += __shfl_down_sync(0xffu, s, o);
        if (t == 0) g_bsum[b] = s;
    }
}

__global__ void scan_pass2(int nb, int n) {
    __shared__ int sw[4];
    int t = threadIdx.x, lane = t & 31, w = t >> 5;
    int v = (t < nb) ? g_bsum[t] : 0;
    int s = v;
    #pragma unroll
    for (int o = 1; o < 32; o <<= 1) {
        int x = __shfl_up_sync(0xffffffffu, s, o);
        if (lane >= o) s += x;
    }
    if (lane == 31) sw[w] = s;
    __syncthreads();
    int pre = 0;
    for (int j = 0; j < w; j++) pre += sw[j];
    int incl = s + pre;
    if (t < nb) g_boff[t] = incl - v;
    if (t == nb - 1) g_row_ptr[n] = incl;
}

__global__ void scan_pass3(int n) {
    __shared__ int swarp[8];
    int b = blockIdx.x, t = threadIdx.x, lane = t & 31, w = t >> 5;
    int i0 = b * 1024 + t * 4;
    int4 v = make_int4(0, 0, 0, 0);
    if (i0 + 3 < n) v = *(const int4*)&g_deg_in[i0];
    else {
        if (i0     < n) v.x = g_deg_in[i0];
        if (i0 + 1 < n) v.y = g_deg_in[i0 + 1];
        if (i0 + 2 < n) v.z = g_deg_in[i0 + 2];
        if (i0 + 3 < n) v.w = g_deg_in[i0 + 3];
    }
    int ts = v.x + v.y + v.z + v.w;
    int s = ts;
    #pragma unroll
    for (int o = 1; o < 32; o <<= 1) {
        int x = __shfl_up_sync(0xffffffffu, s, o);
        if (lane >= o) s += x;
    }
    if (lane == 31) swarp[w] = s;
    __syncthreads();
    if (w == 0 && lane < 8) {
        int ws = swarp[lane];
        #pragma unroll
        for (int o = 1; o < 8; o <<= 1) {
            int x = __shfl_up_sync(0xffu, ws, o);
            if (lane >= o) ws += x;
        }
        swarp[lane] = ws;
    }
    __syncthreads();
    int pre = (w > 0) ? swarp[w - 1] : 0;
    int e0 = g_boff[b] + pre + s - ts;
    int e1 = e0 + v.x, e2 = e1 + v.y, e3 = e2 + v.z;
    if (i0     < n) { g_row_ptr[i0]     = e0; g_cursor[i0]     = e0; }
    if (i0 + 1 < n) { g_row_ptr[i0 + 1] = e1; g_cursor[i0 + 1] = e1; }
    if (i0 + 2 < n) { g_row_ptr[i0 + 2] = e2; g_cursor[i0 + 2] = e2; }
    if (i0 + 3 < n) { g_row_ptr[i0 + 3] = e3; g_cursor[i0 + 3] = e3; }
}

__global__ void csr_fill_kernel(const int* __restrict__ src,
                                const int* __restrict__ dst, int e) {
    int i = blockIdx.x * blockDim.x + threadIdx.x;
    if (i < e) {
        int p = atomicAdd(&g_cursor[dst[i]], 1);
        g_csr_src[p] = src[i];
    }
}

// ---------------------------------------------------------------------------
// Gather-aggregate (standalone, warp-per-node, 4-way MLP unroll).
// ---------------------------------------------------------------------------
template<int DIM, bool RELU, bool HASB, bool SRCSCALE>
__global__ void agg_kernel(const float* __restrict__ hin,
                           float* __restrict__ hout,
                           const float* __restrict__ bias, int n) {
    constexpr int LPN = (DIM >= 32) ? 32 : DIM;
    constexpr int NPW = 32 / LPN;
    int warp = (blockIdx.x * blockDim.x + threadIdx.x) >> 5;
    int lane = threadIdx.x & 31;
    int node = warp * NPW + (lane / LPN);
    int l = lane % LPN;
    if (node >= n) return;
    int beg = g_row_ptr[node];
    int end = g_row_ptr[node + 1];
    float ni = g_norm_in[node];
    if (DIM == 64) {
        const float* base = hin + l * 2;
        float2 a0 = {0, 0}, a1 = {0, 0}, a2 = {0, 0}, a3 = {0, 0};
        int e = beg;
        for (; e + 3 < end; e += 4) {
            int s0 = g_csr_src[e],     s1 = g_csr_src[e + 1];
            int s2 = g_csr_src[e + 2], s3 = g_csr_src[e + 3];
            float2 v0 = *(const float2*)(base + s0 * 64);
            float2 v1 = *(const float2*)(base + s1 * 64);
            float2 v2 = *(const float2*)(base + s2 * 64);
            float2 v3 = *(const float2*)(base + s3 * 64);
            if (SRCSCALE) {
                float n0 = g_norm_out[s0], n1 = g_norm_out[s1];
                float n2 = g_norm_out[s2], n3 = g_norm_out[s3];
                a0.x = fmaf(v0.x, n0, a0.x); a0.y = fmaf(v0.y, n0, a0.y);
                a1.x = fmaf(v1.x, n1, a1.x); a1.y = fmaf(v1.y, n1, a1.y);
                a2.x = fmaf(v2.x, n2, a2.x); a2.y = fmaf(v2.y, n2, a2.y);
                a3.x = fmaf(v3.x, n3, a3.x); a3.y = fmaf(v3.y, n3, a3.y);
            } else {
                a0.x += v0.x; a0.y += v0.y; a1.x += v1.x; a1.y += v1.y;
                a2.x += v2.x; a2.y += v2.y; a3.x += v3.x; a3.y += v3.y;
            }
        }
        for (; e < end; e++) {
            int s0 = g_csr_src[e];
            float2 v = *(const float2*)(base + s0 * 64);
            if (SRCSCALE) {
                float n0 = g_norm_out[s0];
                a0.x = fmaf(v.x, n0, a0.x); a0.y = fmaf(v.y, n0, a0.y);
            } else { a0.x += v.x; a0.y += v.y; }
        }
        float ax = (a0.x + a1.x) + (a2.x + a3.x);
        float ay = (a0.y + a1.y) + (a2.y + a3.y);
        ax *= ni; ay *= ni;
        if (HASB) { ax += bias[l * 2]; ay += bias[l * 2 + 1]; }
        if (RELU) { ax = fmaxf(ax, 0.0f); ay = fmaxf(ay, 0.0f); }
        float2 o; o.x = ax; o.y = ay;
        *(float2*)&hout[node * 64 + l * 2] = o;
    } else {
        const float* base = hin + l;
        float a0 = 0, a1 = 0, a2 = 0, a3 = 0;
        int e = beg;
        for (; e + 3 < end; e += 4) {
            int s0 = g_csr_src[e],     s1 = g_csr_src[e + 1];
            int s2 = g_csr_src[e + 2], s3 = g_csr_src[e + 3];
            a0 += base[s0 * DIM]; a1 += base[s1 * DIM];
            a2 += base[s2 * DIM]; a3 += base[s3 * DIM];
        }
        for (; e < end; e++) a0 += base[g_csr_src[e] * DIM];
        float a = (a0 + a1) + (a2 + a3);
        a *= ni;
        if (HASB) a += bias[l];
        if (RELU) a = fmaxf(a, 0.0f);
        hout[node * DIM + l] = a;
    }
}

// ---------------------------------------------------------------------------
// f32x2 GEMM, fma-bound design:
//   sW[k*M+c] = (W[k][c], W[k][c])        (duplicated at staging)
//   sX[p*K+k] = (in[2p][k], in[2p+1][k])  (row-pair packed at staging)
//   thread: CPT=4 cols x RPT rows (NRP=RPT/2 pairs); zero movs in inner loop.
//   warp covers 8 col-groups x 4 row-groups -> LDS broadcast dedup both ways.
// ---------------------------------------------------------------------------
template<int K, int M, int RPT, bool RELU, bool BIAS, bool RSCALE, int MAXB>
__global__ void __launch_bounds__(256, MAXB)
gemm_kernel(const float* __restrict__ in, const float* __restrict__ W,
            const float* __restrict__ bias, float* __restrict__ out, int n) {
    constexpr int THREADS = 256, CPT = 4;
    constexpr int CG = M / CPT;
    constexpr int RG = THREADS / CG;
    constexpr int NRP = RPT / 2;
    constexpr int RTILE = RG * RPT;
    constexpr int KV = K / 4;
    constexpr int NPAIR = RTILE / 2;
    constexpr int LOADSP = NPAIR * KV / THREADS;
    constexpr int CGH = CG / 8, RGH = RG / 4;
    static_assert(CGH * RGH == 8, "warp tiling must cover 8 warps");

    extern __shared__ char smx[];
    ull* sW = (ull*)smx;                          // K*M ull
    ull* sX = (ull*)(smx + (size_t)K * M * 8);    // NPAIR*K ull

    const int tid = threadIdx.x;
    // Stage W duplicated
    for (int p = tid; p < K * M / 4; p += THREADS) {
        float4 w = ((const float4*)W)[p];
        ull* d = &sW[p * 4];
        d[0] = pk(w.x, w.x); d[1] = pk(w.y, w.y);
        d[2] = pk(w.z, w.z); d[3] = pk(w.w, w.w);
    }

    int lane = tid & 31, wp = tid >> 5;
    int cg = (wp % CGH) * 8 + (lane & 7);
    int rg = (wp / CGH) * 4 + (lane >> 3);
    int c0 = cg * CPT;
    int pbase = rg * NRP;

    float4 bv = make_float4(0.f, 0.f, 0.f, 0.f);
    if (BIAS) bv = *(const float4*)&bias[c0];

    const float4* in4 = (const float4*)in;
    int ntiles = (n + RTILE - 1) / RTILE;
    float4 pfa[LOADSP], pfb[LOADSP];
    int t = blockIdx.x;
    if (t < ntiles) {
        #pragma unroll
        for (int j = 0; j < LOADSP; j++) {
            int idx = tid + j * THREADS;
            int p = idx / KV, k4 = idx % KV;
            int r0 = t * RTILE + 2 * p;
            pfa[j] = (r0     < n) ? in4[(size_t)r0 * KV + k4]       : make_float4(0.f,0.f,0.f,0.f);
            pfb[j] = (r0 + 1 < n) ? in4[(size_t)(r0 + 1) * KV + k4] : make_float4(0.f,0.f,0.f,0.f);
        }
    }
    for (; t < ntiles; t += gridDim.x) {
        int row0 = t * RTILE;
        __syncthreads();
        #pragma unroll
        for (int j = 0; j < LOADSP; j++) {
            int idx = tid + j * THREADS;
            int p = idx / KV, k4 = idx % KV;
            ull* d = &sX[p * K + k4 * 4];
            d[0] = pk(pfa[j].x, pfb[j].x); d[1] = pk(pfa[j].y, pfb[j].y);
            d[2] = pk(pfa[j].z, pfb[j].z); d[3] = pk(pfa[j].w, pfb[j].w);
        }
        __syncthreads();
        int tn = t + gridDim.x;
        if (tn < ntiles) {
            #pragma unroll
            for (int j = 0; j < LOADSP; j++) {
                int idx = tid + j * THREADS;
                int p = idx / KV, k4 = idx % KV;
                int r0 = tn * RTILE + 2 * p;
                pfa[j] = (r0     < n) ? in4[(size_t)r0 * KV + k4]       : make_float4(0.f,0.f,0.f,0.f);
                pfb[j] = (r0 + 1 < n) ? in4[(size_t)(r0 + 1) * KV + k4] : make_float4(0.f,0.f,0.f,0.f);
            }
        }

        ull acc[CPT][NRP];
        #pragma unroll
        for (int c = 0; c < CPT; c++)
            #pragma unroll
            for (int rp = 0; rp < NRP; rp++) acc[c][rp] = 0ULL;

        #pragma unroll 4
        for (int k4 = 0; k4 < KV; k4++) {
            ull xr[NRP][4];
            #pragma unroll
            for (int rp = 0; rp < NRP; rp++) {
                const ull* xp = &sX[(pbase + rp) * K + k4 * 4];
                ulonglong2 xa = *(const ulonglong2*)xp;
                ulonglong2 xb = *(const ulonglong2*)(xp + 2);
                xr[rp][0] = xa.x; xr[rp][1] = xa.y; xr[rp][2] = xb.x; xr[rp][3] = xb.y;
            }
            #pragma unroll
            for (int kk = 0; kk < 4; kk++) {
                int k = k4 * 4 + kk;
                ulonglong2 w0 = *(const ulonglong2*)&sW[k * M + c0];
                ulonglong2 w1 = *(const ulonglong2*)&sW[k * M + c0 + 2];
                #pragma unroll
                for (int rp = 0; rp < NRP; rp++) {
                    fma2(acc[0][rp], xr[rp][kk], w0.x);
                    fma2(acc[1][rp], xr[rp][kk], w0.y);
                    fma2(acc[2][rp], xr[rp][kk], w1.x);
                    fma2(acc[3][rp], xr[rp][kk], w1.y);
                }
            }
        }

        #pragma unroll
        for (int rp = 0; rp < NRP; rp++) {
            int ra = row0 + (pbase + rp) * 2;
            int rb = ra + 1;
            float2 f0 = upk(acc[0][rp]), f1 = upk(acc[1][rp]);
            float2 f2 = upk(acc[2][rp]), f3 = upk(acc[3][rp]);
            float4 va = make_float4(f0.x, f1.x, f2.x, f3.x);
            float4 vb = make_float4(f0.y, f1.y, f2.y, f3.y);
            if (BIAS) {
                va.x += bv.x; va.y += bv.y; va.z += bv.z; va.w += bv.w;
                vb.x += bv.x; vb.y += bv.y; vb.z += bv.z; vb.w += bv.w;
            }
            if (RSCALE) {
                float sa = g_norm_out[min(ra, n - 1)];
                float sb = g_norm_out[min(rb, n - 1)];
                va.x *= sa; va.y *= sa; va.z *= sa; va.w *= sa;
                vb.x *= sb; vb.y *= sb; vb.z *= sb; vb.w *= sb;
            }
            if (RELU) {
                va.x = fmaxf(va.x, 0.f); va.y = fmaxf(va.y, 0.f);
                va.z = fmaxf(va.z, 0.f); va.w = fmaxf(va.w, 0.f);
                vb.x = fmaxf(vb.x, 0.f); vb.y = fmaxf(vb.y, 0.f);
                vb.z = fmaxf(vb.z, 0.f); vb.w = fmaxf(vb.w, 0.f);
            }
            if (ra < n) *(float4*)&out[(size_t)ra * M + c0] = va;
            if (rb < n) *(float4*)&out[(size_t)rb * M + c0] = vb;
        }
    }
}

// Final tiny GEMM: K=32, M=4, one row per thread, fused norm_out.
__global__ void gemm4_kernel(const float* __restrict__ in,
                             const float* __restrict__ W,
                             float* __restrict__ out, int n) {
    __shared__ float4 sw[32];
    if (threadIdx.x < 32) sw[threadIdx.x] = *(const float4*)&W[threadIdx.x * 4];
    __syncthreads();
    int r = blockIdx.x * blockDim.x + threadIdx.x;
    if (r >= n) return;
    const float* x = in + (size_t)r * 32;
    float4 acc = make_float4(0.f, 0.f, 0.f, 0.f);
    #pragma unroll
    for (int k4 = 0; k4 < 8; k4++) {
        float4 xv = *(const float4*)&x[k4 * 4];
        float4 w0 = sw[k4 * 4], w1 = sw[k4 * 4 + 1], w2 = sw[k4 * 4 + 2], w3 = sw[k4 * 4 + 3];
        acc.x = fmaf(xv.x, w0.x, fmaf(xv.y, w1.x, fmaf(xv.z, w2.x, fmaf(xv.w, w3.x, acc.x))));
        acc.y = fmaf(xv.x, w0.y, fmaf(xv.y, w1.y, fmaf(xv.z, w2.y, fmaf(xv.w, w3.y, acc.y))));
        acc.z = fmaf(xv.x, w0.z, fmaf(xv.y, w1.z, fmaf(xv.z, w2.z, fmaf(xv.w, w3.z, acc.z))));
        acc.w = fmaf(xv.x, w0.w, fmaf(xv.y, w1.w, fmaf(xv.z, w2.w, fmaf(xv.w, w3.w, acc.w))));
    }
    float s = g_norm_out[r];
    acc.x *= s; acc.y *= s; acc.z *= s; acc.w *= s;
    *(float4*)&out[(size_t)r * 4] = acc;
}

// ---------------------------------------------------------------------------
// Final: agg(h,4) * norm_in + b4 -> per-graph sum + count (gids sorted).
// ---------------------------------------------------------------------------
__global__ void agg4_readout(const float* __restrict__ hin,
                             const float* __restrict__ b4,
                             const int* __restrict__ gid, int n) {
    int warp = (blockIdx.x * blockDim.x + threadIdx.x) >> 5;
    int lane = threadIdx.x & 31;
    int node = warp * 8 + (lane >> 2);
    int l = lane & 3;
    float v = 0.f;
    int g = 0;
    bool valid = node < n;
    if (valid) {
        int beg = g_row_ptr[node], end = g_row_ptr[node + 1];
        float a0 = 0, a1 = 0, a2 = 0, a3 = 0;
        int e = beg;
        for (; e + 3 < end; e += 4) {
            a0 += hin[g_csr_src[e] * 4 + l];
            a1 += hin[g_csr_src[e + 1] * 4 + l];
            a2 += hin[g_csr_src[e + 2] * 4 + l];
            a3 += hin[g_csr_src[e + 3] * 4 + l];
        }
        for (; e < end; e++) a0 += hin[g_csr_src[e] * 4 + l];
        v = fmaf(((a0 + a1) + (a2 + a3)), g_norm_in[node], b4[l]);
        g = gid[node];
    }
    unsigned act = __ballot_sync(0xffffffffu, valid);
    if (act == 0xffffffffu) {
        int g0 = __shfl_sync(0xffffffffu, g, 0);
        if (__all_sync(0xffffffffu, g == g0)) {
            v += __shfl_xor_sync(0xffffffffu, v, 4);
            v += __shfl_xor_sync(0xffffffffu, v, 8);
            v += __shfl_xor_sync(0xffffffffu, v, 16);
            if (lane < 4) atomicAdd(&g_gsum[g0 * 4 + lane], v);
            if (lane == 0) atomicAdd(&g_gcnt[g0], 8);
            return;
        }
    }
    if (valid) {
        atomicAdd(&g_gsum[g * 4 + l], v);
        if (l == 0) atomicAdd(&g_gcnt[g], 1);
    }
}

__global__ void graph_mean_kernel(float* __restrict__ out, int g) {
    int i = blockIdx.x * blockDim.x + threadIdx.x;
    if (i < g * 4) {
        float c = fmaxf((float)g_gcnt[i >> 2], 1.0f);
        out[i] = g_gsum[i] / c;
    }
}

// ---------------------------------------------------------------------------
extern "C" void kernel_launch(void* const* d_in, const int* in_sizes, int n_in,
                              void* d_out, int out_size) {
    const float* x  = (const float*)d_in[0];
    const float* W1 = (const float*)d_in[1];
    const float* b1 = (const float*)d_in[2];
    const float* W2 = (const float*)d_in[3];
    const float* b2 = (const float*)d_in[4];
    const float* W3 = (const float*)d_in[5];
    const float* b3 = (const float*)d_in[6];
    const float* W4 = (const float*)d_in[7];
    const float* b4 = (const float*)d_in[8];
    const int* src = (const int*)d_in[9];
    const int* dst = (const int*)d_in[10];
    const int* gid = (const int*)d_in[11];
    float* out = (float*)d_out;

    int n = in_sizes[0] / 64;
    int e = in_sizes[9];
    int g = out_size / 4;

    float *h0, *h1;
    cudaGetSymbolAddress((void**)&h0, g_h0);
    cudaGetSymbolAddress((void**)&h1, g_h1);

    const int T = 256;
    auto blocks = [](int work, int t) { return (work + t - 1) / t; };
    auto agg_grid = [&](int npw) {
        int warps = (n + npw - 1) / npw;
        return (warps * 32 + T - 1) / T;
    };

    // GEMM smem: sW = K*M*8 B (duplicated), sX = (RTILE/2)*K*8 B (paired)
    // gemm1: K=64,M=128,RPT=8 -> RTILE=64:  64K + 16K = 80K  (2/SM)
    // gemm2: K=128,M=64,RPT=4 -> RTILE=64:  64K + 32K = 96K  (2/SM)
    // gemm3: K=64,M=32, RPT=4 -> RTILE=128: 16K + 32K = 48K  (4/SM)
    const int SM1 = 64 * 128 * 8 + 32 * 64 * 8;
    const int SM2 = 128 * 64 * 8 + 32 * 128 * 8;
    const int SM3 = 64 * 32 * 8 + 64 * 64 * 8;
    cudaFuncSetAttribute((const void*)gemm_kernel<64, 128, 8, true, true, false, 2>,
                         cudaFuncAttributeMaxDynamicSharedMemorySize, SM1);
    cudaFuncSetAttribute((const void*)gemm_kernel<128, 64, 4, false, false, true, 2>,
                         cudaFuncAttributeMaxDynamicSharedMemorySize, SM2);
    cudaFuncSetAttribute((const void*)gemm_kernel<64, 32, 4, false, false, true, 4>,
                         cudaFuncAttributeMaxDynamicSharedMemorySize, SM3);

    int nb = (n + 1023) / 1024;
    zero_kernel<<<blocks(n, T), T>>>(n, g);
    degree_kernel<<<blocks(e, T), T>>>(src, dst, e);
    scan_pass1<<<nb, 256>>>(n);
    scan_pass2<<<1, 128>>>(nb, n);
    scan_pass3<<<nb, 256>>>(n);
    csr_fill_kernel<<<blocks(e, T), T>>>(src, dst, e);

    // Layer 1: agg(x * norm_out) -> *norm_in -> @W1 + b1, relu
    agg_kernel<64, false, false, true><<<agg_grid(1), T>>>(x, h1, nullptr, n);
    gemm_kernel<64, 128, 8, true, true, false, 2><<<296, 256, SM1>>>(h1, W1, b1, h0, n);

    // Layer 2: (h @ W2) * norm_out -> agg -> *norm_in + b2, relu
    gemm_kernel<128, 64, 4, false, false, true, 2><<<296, 256, SM2>>>(h0, W2, nullptr, h1, n);
    agg_kernel<64, true, true, false><<<agg_grid(1), T>>>(h1, h0, b2, n);

    // Layer 3
    gemm_kernel<64, 32, 4, false, false, true, 4><<<592, 256, SM3>>>(h0, W3, nullptr, h1, n);
    agg_kernel<32, true, true, false><<<agg_grid(1), T>>>(h1, h0, b3, n);

    // Layer 4 + readout
    gemm4_kernel<<<blocks(n, T), T>>>(h0, W4, h1, n);
    int warps4 = (n + 7) / 8;
    agg4_readout<<<blocks(warps4 * 32, T), T>>>(h1, b4, gid, n);
    graph_mean_kernel<<<blocks(g * 4, T), T>>>(out, g);
}

// round 7
// speedup vs baseline: 1.0778x; 1.0778x over previous
#include <cuda_runtime.h>
#include <cuda_bf16.h>

// ---------------------------------------------------------------------------
// GCN 4-layer forward on GB300 (sm_103a).
// R6: exact R2 structure (best measured), with three surgical changes:
//  1. GEMM sW layout padded to stride K+4 -> conflict-free W LDS.128.
//  2. norm computation fused into scan_pass1 (one fewer launch).
//  3. agg<4> + graph_sum fused into agg4_readout.
// ---------------------------------------------------------------------------

#define MAX_N 100000
#define MAX_E 800000
#define MAX_G 500

__device__ float g_norm_out[MAX_N];
__device__ float g_norm_in[MAX_N];
__device__ int   g_deg_out[MAX_N];
__device__ int   g_deg_in[MAX_N];
__device__ int   g_row_ptr[MAX_N + 1];
__device__ int   g_cursor[MAX_N];
__device__ int   g_csr_src[MAX_E];
__device__ float g_h0[MAX_N * 128];
__device__ float g_h1[MAX_N * 128];
__device__ float g_gsum[MAX_G * 4];
__device__ int   g_gcnt[MAX_G];
__device__ int   g_bsum[128];
__device__ int   g_boff[128];

// ---------------------------------------------------------------------------
__global__ void zero_kernel(int n, int g) {
    int i = blockIdx.x * blockDim.x + threadIdx.x;
    if (i < n) { g_deg_out[i] = 0; g_deg_in[i] = 0; }
    if (i < g * 4) g_gsum[i] = 0.0f;
    if (i < g) g_gcnt[i] = 0;
}

__global__ void degree_kernel(const int* __restrict__ src,
                              const int* __restrict__ dst, int e) {
    int i = blockIdx.x * blockDim.x + threadIdx.x;
    if (i < e) {
        atomicAdd(&g_deg_out[src[i]], 1);
        atomicAdd(&g_deg_in[dst[i]], 1);
    }
}

// pass1 with norm computation fused
__global__ void scan_pass1(int n) {
    __shared__ int sw[8];
    int b = blockIdx.x, t = threadIdx.x;
    int i0 = b * 1024 + t * 4;
    int s = 0;
    #pragma unroll
    for (int j = 0; j < 4; j++) {
        int i = i0 + j;
        if (i < n) {
            int di = g_deg_in[i];
            s += di;
            g_norm_in[i]  = rsqrtf(fmaxf((float)di, 1.0f));
            g_norm_out[i] = rsqrtf(fmaxf((float)g_deg_out[i], 1.0f));
        }
    }
    #pragma unroll
    for (int o = 16; o; o >>= 1) s += __shfl_down_sync(0xffffffffu, s, o);
    if ((t & 31) == 0) sw[t >> 5] = s;
    __syncthreads();
    if (t < 8) {
        s = sw[t];
        #pragma unroll
        for (int o = 4; o; o >>= 1) s += __shfl_down_sync(0xffu, s, o);
        if (t == 0) g_bsum[b] = s;
    }
}

__global__ void scan_pass2(int nb, int n) {
    __shared__ int sw[4];
    int t = threadIdx.x, lane = t & 31, w = t >> 5;
    int v = (t < nb) ? g_bsum[t] : 0;
    int s = v;
    #pragma unroll
    for (int o = 1; o < 32; o <<= 1) {
        int x = __shfl_up_sync(0xffffffffu, s, o);
        if (lane >= o) s += x;
    }
    if (lane == 31) sw[w] = s;
    __syncthreads();
    int pre = 0;
    for (int j = 0; j < w; j++) pre += sw[j];
    int incl = s + pre;
    if (t < nb) g_boff[t] = incl - v;
    if (t == nb - 1) g_row_ptr[n] = incl;
}

__global__ void scan_pass3(int n) {
    __shared__ int swarp[8];
    int b = blockIdx.x, t = threadIdx.x, lane = t & 31, w = t >> 5;
    int i0 = b * 1024 + t * 4;
    int4 v = make_int4(0, 0, 0, 0);
    if (i0 + 3 < n) v = *(const int4*)&g_deg_in[i0];
    else {
        if (i0     < n) v.x = g_deg_in[i0];
        if (i0 + 1 < n) v.y = g_deg_in[i0 + 1];
        if (i0 + 2 < n) v.z = g_deg_in[i0 + 2];
        if (i0 + 3 < n) v.w = g_deg_in[i0 + 3];
    }
    int ts = v.x + v.y + v.z + v.w;
    int s = ts;
    #pragma unroll
    for (int o = 1; o < 32; o <<= 1) {
        int x = __shfl_up_sync(0xffffffffu, s, o);
        if (lane >= o) s += x;
    }
    if (lane == 31) swarp[w] = s;
    __syncthreads();
    if (w == 0 && lane < 8) {
        int ws = swarp[lane];
        #pragma unroll
        for (int o = 1; o < 8; o <<= 1) {
            int x = __shfl_up_sync(0xffu, ws, o);
            if (lane >= o) ws += x;
        }
        swarp[lane] = ws;
    }
    __syncthreads();
    int pre = (w > 0) ? swarp[w - 1] : 0;
    int e0 = g_boff[b] + pre + s - ts;
    int e1 = e0 + v.x, e2 = e1 + v.y, e3 = e2 + v.z;
    if (i0     < n) { g_row_ptr[i0]     = e0; g_cursor[i0]     = e0; }
    if (i0 + 1 < n) { g_row_ptr[i0 + 1] = e1; g_cursor[i0 + 1] = e1; }
    if (i0 + 2 < n) { g_row_ptr[i0 + 2] = e2; g_cursor[i0 + 2] = e2; }
    if (i0 + 3 < n) { g_row_ptr[i0 + 3] = e3; g_cursor[i0 + 3] = e3; }
}

__global__ void csr_fill_kernel(const int* __restrict__ src,
                                const int* __restrict__ dst, int e) {
    int i = blockIdx.x * blockDim.x + threadIdx.x;
    if (i < e) {
        int p = atomicAdd(&g_cursor[dst[i]], 1);
        g_csr_src[p] = src[i];
    }
}

// h0[i,:] = x[i,:] * norm_out[i]   (64 floats/row = 16 float4)
__global__ void scale_x_kernel(const float* __restrict__ x, int n) {
    int i = blockIdx.x * blockDim.x + threadIdx.x;
    if (i < n * 16) {
        int row = i >> 4;
        float s = g_norm_out[row];
        float4 v = ((const float4*)x)[i];
        v.x *= s; v.y *= s; v.z *= s; v.w *= s;
        ((float4*)g_h0)[i] = v;
    }
}

// ---------------------------------------------------------------------------
// Gather-aggregate (R2 verbatim): warp/node, 4-way MLP unroll.
// ---------------------------------------------------------------------------
template<int DIM, bool RELU, bool HASB>
__global__ void agg_kernel(const float* __restrict__ hin,
                           float* __restrict__ hout,
                           const float* __restrict__ bias, int n) {
    constexpr int LPN = (DIM >= 32) ? 32 : DIM;
    constexpr int NPW = 32 / LPN;
    int warp = (blockIdx.x * blockDim.x + threadIdx.x) >> 5;
    int lane = threadIdx.x & 31;
    int node = warp * NPW + (lane / LPN);
    int l = lane % LPN;
    if (node >= n) return;
    int beg = g_row_ptr[node];
    int end = g_row_ptr[node + 1];
    float ni = g_norm_in[node];
    if (DIM == 64) {
        const float* base = hin + l * 2;
        float2 a0 = {0, 0}, a1 = {0, 0}, a2 = {0, 0}, a3 = {0, 0};
        int e = beg;
        for (; e + 3 < end; e += 4) {
            int s0 = g_csr_src[e],     s1 = g_csr_src[e + 1];
            int s2 = g_csr_src[e + 2], s3 = g_csr_src[e + 3];
            float2 v0 = *(const float2*)(base + s0 * 64);
            float2 v1 = *(const float2*)(base + s1 * 64);
            float2 v2 = *(const float2*)(base + s2 * 64);
            float2 v3 = *(const float2*)(base + s3 * 64);
            a0.x += v0.x; a0.y += v0.y; a1.x += v1.x; a1.y += v1.y;
            a2.x += v2.x; a2.y += v2.y; a3.x += v3.x; a3.y += v3.y;
        }
        for (; e < end; e++) {
            float2 v = *(const float2*)(base + g_csr_src[e] * 64);
            a0.x += v.x; a0.y += v.y;
        }
        float ax = (a0.x + a1.x) + (a2.x + a3.x);
        float ay = (a0.y + a1.y) + (a2.y + a3.y);
        ax *= ni; ay *= ni;
        if (HASB) { ax += bias[l * 2]; ay += bias[l * 2 + 1]; }
        if (RELU) { ax = fmaxf(ax, 0.0f); ay = fmaxf(ay, 0.0f); }
        float2 o; o.x = ax; o.y = ay;
        *(float2*)&hout[node * 64 + l * 2] = o;
    } else {
        const float* base = hin + l;
        float a0 = 0, a1 = 0, a2 = 0, a3 = 0;
        int e = beg;
        for (; e + 3 < end; e += 4) {
            int s0 = g_csr_src[e],     s1 = g_csr_src[e + 1];
            int s2 = g_csr_src[e + 2], s3 = g_csr_src[e + 3];
            a0 += base[s0 * DIM]; a1 += base[s1 * DIM];
            a2 += base[s2 * DIM]; a3 += base[s3 * DIM];
        }
        for (; e < end; e++) a0 += base[g_csr_src[e] * DIM];
        float a = (a0 + a1) + (a2 + a3);
        a *= ni;
        if (HASB) a += bias[l];
        if (RELU) a = fmaxf(a, 0.0f);
        hout[node * DIM + l] = a;
    }
}

// ---------------------------------------------------------------------------
// Dense GEMM (R2 design; ONLY change: sW stride padded to K+4 so the per-k4
// W LDS.128 is bank-conflict-free across the warp's consecutive columns).
// ---------------------------------------------------------------------------
template<int K, int M, bool RELU>
__global__ void __launch_bounds__(256, 2)
gemm_kernel(const float* __restrict__ in,
            const float* __restrict__ W,
            const float* __restrict__ bias,
            const float* __restrict__ rowscale,
            float* __restrict__ out, int n) {
    constexpr int THREADS = 256;
    constexpr int RPAR = THREADS / M;
    constexpr int RPT = 4;
    constexpr int RTILE = RPAR * RPT;
    constexpr int KP = K + 4;              // padded column stride
    __shared__ float sW[KP * M];           // sW[col*KP + k]
    __shared__ float sIn[RTILE * K];

    for (int idx = threadIdx.x; idx < K * M; idx += THREADS) {
        int k = idx / M, c = idx % M;
        sW[c * KP + k] = W[idx];
    }
    __syncthreads();

    int col = threadIdx.x % M;
    int rg  = threadIdx.x / M;
    const float4* wt = (const float4*)&sW[col * KP];

    int ntiles = (n + RTILE - 1) / RTILE;
    for (int t = blockIdx.x; t < ntiles; t += gridDim.x) {
        int row0 = t * RTILE;
        int rows = min(RTILE, n - row0);
        __syncthreads();
        {
            const float4* gin = (const float4*)&in[(long)row0 * K];
            float4* s4 = (float4*)sIn;
            int nv = rows * K / 4;
            for (int idx = threadIdx.x; idx < nv; idx += THREADS)
                s4[idx] = gin[idx];
        }
        __syncthreads();
        float acc[RPT];
        #pragma unroll
        for (int r = 0; r < RPT; r++) acc[r] = 0.0f;
        #pragma unroll
        for (int k4 = 0; k4 < K / 4; k4++) {
            float4 w = wt[k4];
            #pragma unroll
            for (int r = 0; r < RPT; r++) {
                int rr = rg + r * RPAR;
                float4 x = *(const float4*)&sIn[rr * K + k4 * 4];
                acc[r] = fmaf(w.x, x.x,
                         fmaf(w.y, x.y,
                         fmaf(w.z, x.z,
                         fmaf(w.w, x.w, acc[r]))));
            }
        }
        #pragma unroll
        for (int r = 0; r < RPT; r++) {
            int rr = rg + r * RPAR;
            if (rr < rows) {
                int row = row0 + rr;
                float v = acc[r];
                if (bias) v += bias[col];
                if (rowscale) v *= rowscale[row];
                if (RELU) v = fmaxf(v, 0.0f);
                out[(long)row * M + col] = v;
            }
        }
    }
}

// Final tiny GEMM: K=32, M=4, one row per thread, fused rowscale.
__global__ void gemm4_kernel(const float* __restrict__ in,
                             const float* __restrict__ W,
                             const float* __restrict__ rowscale,
                             float* __restrict__ out, int n) {
    __shared__ float4 sw[32];
    if (threadIdx.x < 32) sw[threadIdx.x] = *(const float4*)&W[threadIdx.x * 4];
    __syncthreads();
    int r = blockIdx.x * blockDim.x + threadIdx.x;
    if (r >= n) return;
    const float* x = in + (size_t)r * 32;
    float4 acc = make_float4(0.f, 0.f, 0.f, 0.f);
    #pragma unroll
    for (int k4 = 0; k4 < 8; k4++) {
        float4 xv = *(const float4*)&x[k4 * 4];
        float4 w0 = sw[k4 * 4], w1 = sw[k4 * 4 + 1], w2 = sw[k4 * 4 + 2], w3 = sw[k4 * 4 + 3];
        acc.x = fmaf(xv.x, w0.x, fmaf(xv.y, w1.x, fmaf(xv.z, w2.x, fmaf(xv.w, w3.x, acc.x))));
        acc.y = fmaf(xv.x, w0.y, fmaf(xv.y, w1.y, fmaf(xv.z, w2.y, fmaf(xv.w, w3.y, acc.y))));
        acc.z = fmaf(xv.x, w0.z, fmaf(xv.y, w1.z, fmaf(xv.z, w2.z, fmaf(xv.w, w3.z, acc.z))));
        acc.w = fmaf(xv.x, w0.w, fmaf(xv.y, w1.w, fmaf(xv.z, w2.w, fmaf(xv.w, w3.w, acc.w))));
    }
    float s = rowscale[r];
    acc.x *= s; acc.y *= s; acc.z *= s; acc.w *= s;
    *(float4*)&out[(size_t)r * 4] = acc;
}

// ---------------------------------------------------------------------------
// Fused final aggregation + per-graph readout (gids sorted).
// ---------------------------------------------------------------------------
__global__ void agg4_readout(const float* __restrict__ hin,
                             const float* __restrict__ b4,
                             const int* __restrict__ gid, int n) {
    int warp = (blockIdx.x * blockDim.x + threadIdx.x) >> 5;
    int lane = threadIdx.x & 31;
    int node = warp * 8 + (lane >> 2);
    int l = lane & 3;
    float v = 0.f;
    int g = 0;
    bool valid = node < n;
    if (valid) {
        int beg = g_row_ptr[node], end = g_row_ptr[node + 1];
        float a0 = 0, a1 = 0, a2 = 0, a3 = 0;
        int e = beg;
        for (; e + 3 < end; e += 4) {
            a0 += hin[g_csr_src[e] * 4 + l];
            a1 += hin[g_csr_src[e + 1] * 4 + l];
            a2 += hin[g_csr_src[e + 2] * 4 + l];
            a3 += hin[g_csr_src[e + 3] * 4 + l];
        }
        for (; e < end; e++) a0 += hin[g_csr_src[e] * 4 + l];
        v = fmaf(((a0 + a1) + (a2 + a3)), g_norm_in[node], b4[l]);
        g = gid[node];
    }
    unsigned act = __ballot_sync(0xffffffffu, valid);
    if (act == 0xffffffffu) {
        int g0 = __shfl_sync(0xffffffffu, g, 0);
        if (__all_sync(0xffffffffu, g == g0)) {
            v += __shfl_xor_sync(0xffffffffu, v, 4);
            v += __shfl_xor_sync(0xffffffffu, v, 8);
            v += __shfl_xor_sync(0xffffffffu, v, 16);
            if (lane < 4) atomicAdd(&g_gsum[g0 * 4 + lane], v);
            if (lane == 0) atomicAdd(&g_gcnt[g0], 8);
            return;
        }
    }
    if (valid) {
        atomicAdd(&g_gsum[g * 4 + l], v);
        if (l == 0) atomicAdd(&g_gcnt[g], 1);
    }
}

__global__ void graph_mean_kernel(float* __restrict__ out, int g) {
    int i = blockIdx.x * blockDim.x + threadIdx.x;
    if (i < g * 4) {
        float c = fmaxf((float)g_gcnt[i >> 2], 1.0f);
        out[i] = g_gsum[i] / c;
    }
}

// ---------------------------------------------------------------------------
extern "C" void kernel_launch(void* const* d_in, const int* in_sizes, int n_in,
                              void* d_out, int out_size) {
    const float* x  = (const float*)d_in[0];
    const float* W1 = (const float*)d_in[1];
    const float* b1 = (const float*)d_in[2];
    const float* W2 = (const float*)d_in[3];
    const float* b2 = (const float*)d_in[4];
    const float* W3 = (const float*)d_in[5];
    const float* b3 = (const float*)d_in[6];
    const float* W4 = (const float*)d_in[7];
    const float* b4 = (const float*)d_in[8];
    const int* src = (const int*)d_in[9];
    const int* dst = (const int*)d_in[10];
    const int* gid = (const int*)d_in[11];
    float* out = (float*)d_out;

    int n = in_sizes[0] / 64;   // nodes
    int e = in_sizes[9];        // edges
    int g = out_size / 4;       // graphs

    float *h0, *h1, *nrm_out;
    cudaGetSymbolAddress((void**)&h0, g_h0);
    cudaGetSymbolAddress((void**)&h1, g_h1);
    cudaGetSymbolAddress((void**)&nrm_out, g_norm_out);

    const int T = 256;
    auto blocks = [](int work, int t) { return (work + t - 1) / t; };
    auto agg_grid = [&](int npw) {
        int warps = (n + npw - 1) / npw;
        return (warps * 32 + T - 1) / T;
    };

    // Graph preprocessing
    int nb = (n + 1023) / 1024;
    zero_kernel<<<blocks(n, T), T>>>(n, g);
    degree_kernel<<<blocks(e, T), T>>>(src, dst, e);
    scan_pass1<<<nb, 256>>>(n);
    scan_pass2<<<1, 128>>>(nb, n);
    scan_pass3<<<nb, 256>>>(n);
    csr_fill_kernel<<<blocks(e, T), T>>>(src, dst, e);

    const int GEMM_GRID = 296;  // 148 SMs * 2

    // Layer 1: agg(x * norm_out) -> (* norm_in) -> @W1 + b1 -> relu
    scale_x_kernel<<<blocks(n * 16, T), T>>>(x, n);
    agg_kernel<64, false, false><<<agg_grid(1), T>>>(h0, h1, nullptr, n);
    gemm_kernel<64, 128, true><<<GEMM_GRID, T>>>(h1, W1, b1, nullptr, h0, n);

    // Layer 2: (h @ W2) * norm_out -> agg -> * norm_in + b2 -> relu
    gemm_kernel<128, 64, false><<<GEMM_GRID, T>>>(h0, W2, nullptr, nrm_out, h1, n);
    agg_kernel<64, true, true><<<agg_grid(1), T>>>(h1, h0, b2, n);

    // Layer 3
    gemm_kernel<64, 32, false><<<GEMM_GRID, T>>>(h0, W3, nullptr, nrm_out, h1, n);
    agg_kernel<32, true, true><<<agg_grid(1), T>>>(h1, h0, b3, n);

    // Layer 4 (no relu) + fused readout
    gemm4_kernel<<<blocks(n, T), T>>>(h0, W4, nrm_out, h1, n);
    int warps4 = (n + 7) / 8;
    agg4_readout<<<blocks(warps4 * 32, T), T>>>(h1, b4, gid, n);
    graph_mean_kernel<<<blocks(g * 4, T), T>>>(out, g);
}

// round 8
// speedup vs baseline: 1.1234x; 1.0423x over previous
#include <cuda_runtime.h>

// ---------------------------------------------------------------------------
// GCN 4-layer forward on GB300 (sm_103a).
// R7: R6 skeleton + (1) colpair f32x2 GEMM (minimal mutation of R2 loop,
// both operands packed at staging, zero inner-loop movs), (2) norm_out folded
// into layer-1 gather (scale_x removed), (3) gemm4 fused into agg32 epilogue.
// ---------------------------------------------------------------------------

#define MAX_N 100000
#define MAX_E 800000
#define MAX_G 500

__device__ float g_norm_out[MAX_N];
__device__ float g_norm_in[MAX_N];
__device__ int   g_deg_out[MAX_N];
__device__ int   g_deg_in[MAX_N];
__device__ int   g_row_ptr[MAX_N + 1];
__device__ int   g_cursor[MAX_N];
__device__ int   g_csr_src[MAX_E];
__device__ float g_h0[MAX_N * 128];
__device__ float g_h1[MAX_N * 64];
__device__ float g_gsum[MAX_G * 4];
__device__ int   g_gcnt[MAX_G];
__device__ int   g_bsum[128];
__device__ int   g_boff[128];

typedef unsigned long long ull;

__device__ __forceinline__ ull pk(float lo, float hi) {
    ull r; asm("mov.b64 %0, {%1,%2};" : "=l"(r) : "f"(lo), "f"(hi)); return r;
}
__device__ __forceinline__ void fma2(ull& d, ull a, ull b) {
    asm("fma.rn.f32x2 %0, %1, %2, %0;" : "+l"(d) : "l"(a), "l"(b));
}
__device__ __forceinline__ float2 upk(ull v) {
    float2 f; asm("mov.b64 {%0,%1}, %2;" : "=f"(f.x), "=f"(f.y) : "l"(v)); return f;
}

// ---------------------------------------------------------------------------
// Preprocessing
// ---------------------------------------------------------------------------
__global__ void zero_kernel(int n, int g) {
    int i = blockIdx.x * blockDim.x + threadIdx.x;
    if (i < n) { g_deg_out[i] = 0; g_deg_in[i] = 0; }
    if (i < g * 4) g_gsum[i] = 0.0f;
    if (i < g) g_gcnt[i] = 0;
}

__global__ void degree_kernel(const int* __restrict__ src,
                              const int* __restrict__ dst, int e) {
    int i = blockIdx.x * blockDim.x + threadIdx.x;
    if (i < e) {
        atomicAdd(&g_deg_out[src[i]], 1);
        atomicAdd(&g_deg_in[dst[i]], 1);
    }
}

// pass1 with norm computation fused
__global__ void scan_pass1(int n) {
    __shared__ int sw[8];
    int b = blockIdx.x, t = threadIdx.x;
    int i0 = b * 1024 + t * 4;
    int s = 0;
    #pragma unroll
    for (int j = 0; j < 4; j++) {
        int i = i0 + j;
        if (i < n) {
            int di = g_deg_in[i];
            s += di;
            g_norm_in[i]  = rsqrtf(fmaxf((float)di, 1.0f));
            g_norm_out[i] = rsqrtf(fmaxf((float)g_deg_out[i], 1.0f));
        }
    }
    #pragma unroll
    for (int o = 16; o; o >>= 1) s += __shfl_down_sync(0xffffffffu, s, o);
    if ((t & 31) == 0) sw[t >> 5] = s;
    __syncthreads();
    if (t < 8) {
        s = sw[t];
        #pragma unroll
        for (int o = 4; o; o >>= 1) s += __shfl_down_sync(0xffu, s, o);
        if (t == 0) g_bsum[b] = s;
    }
}

__global__ void scan_pass2(int nb, int n) {
    __shared__ int sw[4];
    int t = threadIdx.x, lane = t & 31, w = t >> 5;
    int v = (t < nb) ? g_bsum[t] : 0;
    int s = v;
    #pragma unroll
    for (int o = 1; o < 32; o <<= 1) {
        int x = __shfl_up_sync(0xffffffffu, s, o);
        if (lane >= o) s += x;
    }
    if (lane == 31) sw[w] = s;
    __syncthreads();
    int pre = 0;
    for (int j = 0; j < w; j++) pre += sw[j];
    int incl = s + pre;
    if (t < nb) g_boff[t] = incl - v;
    if (t == nb - 1) g_row_ptr[n] = incl;
}

__global__ void scan_pass3(int n) {
    __shared__ int swarp[8];
    int b = blockIdx.x, t = threadIdx.x, lane = t & 31, w = t >> 5;
    int i0 = b * 1024 + t * 4;
    int4 v = make_int4(0, 0, 0, 0);
    if (i0 + 3 < n) v = *(const int4*)&g_deg_in[i0];
    else {
        if (i0     < n) v.x = g_deg_in[i0];
        if (i0 + 1 < n) v.y = g_deg_in[i0 + 1];
        if (i0 + 2 < n) v.z = g_deg_in[i0 + 2];
        if (i0 + 3 < n) v.w = g_deg_in[i0 + 3];
    }
    int ts = v.x + v.y + v.z + v.w;
    int s = ts;
    #pragma unroll
    for (int o = 1; o < 32; o <<= 1) {
        int x = __shfl_up_sync(0xffffffffu, s, o);
        if (lane >= o) s += x;
    }
    if (lane == 31) swarp[w] = s;
    __syncthreads();
    if (w == 0 && lane < 8) {
        int ws = swarp[lane];
        #pragma unroll
        for (int o = 1; o < 8; o <<= 1) {
            int x = __shfl_up_sync(0xffu, ws, o);
            if (lane >= o) ws += x;
        }
        swarp[lane] = ws;
    }
    __syncthreads();
    int pre = (w > 0) ? swarp[w - 1] : 0;
    int e0 = g_boff[b] + pre + s - ts;
    int e1 = e0 + v.x, e2 = e1 + v.y, e3 = e2 + v.z;
    if (i0     < n) { g_row_ptr[i0]     = e0; g_cursor[i0]     = e0; }
    if (i0 + 1 < n) { g_row_ptr[i0 + 1] = e1; g_cursor[i0 + 1] = e1; }
    if (i0 + 2 < n) { g_row_ptr[i0 + 2] = e2; g_cursor[i0 + 2] = e2; }
    if (i0 + 3 < n) { g_row_ptr[i0 + 3] = e3; g_cursor[i0 + 3] = e3; }
}

__global__ void csr_fill_kernel(const int* __restrict__ src,
                                const int* __restrict__ dst, int e) {
    int i = blockIdx.x * blockDim.x + threadIdx.x;
    if (i < e) {
        int p = atomicAdd(&g_cursor[dst[i]], 1);
        g_csr_src[p] = src[i];
    }
}

// ---------------------------------------------------------------------------
// Gather-aggregate: warp/node, 4-way MLP unroll. SRCSCALE folds norm_out[src].
// ---------------------------------------------------------------------------
template<int DIM, bool RELU, bool HASB, bool SRCSCALE>
__global__ void agg_kernel(const float* __restrict__ hin,
                           float* __restrict__ hout,
                           const float* __restrict__ bias, int n) {
    int warp = (blockIdx.x * blockDim.x + threadIdx.x) >> 5;
    int lane = threadIdx.x & 31;
    int node = warp;
    int l = lane;
    if (node >= n) return;
    int beg = g_row_ptr[node];
    int end = g_row_ptr[node + 1];
    float ni = g_norm_in[node];
    const float* base = hin + l * 2;
    float2 a0 = {0, 0}, a1 = {0, 0}, a2 = {0, 0}, a3 = {0, 0};
    int e = beg;
    for (; e + 3 < end; e += 4) {
        int s0 = g_csr_src[e],     s1 = g_csr_src[e + 1];
        int s2 = g_csr_src[e + 2], s3 = g_csr_src[e + 3];
        float2 v0 = *(const float2*)(base + s0 * DIM);
        float2 v1 = *(const float2*)(base + s1 * DIM);
        float2 v2 = *(const float2*)(base + s2 * DIM);
        float2 v3 = *(const float2*)(base + s3 * DIM);
        if (SRCSCALE) {
            float n0 = g_norm_out[s0], n1 = g_norm_out[s1];
            float n2 = g_norm_out[s2], n3 = g_norm_out[s3];
            a0.x = fmaf(v0.x, n0, a0.x); a0.y = fmaf(v0.y, n0, a0.y);
            a1.x = fmaf(v1.x, n1, a1.x); a1.y = fmaf(v1.y, n1, a1.y);
            a2.x = fmaf(v2.x, n2, a2.x); a2.y = fmaf(v2.y, n2, a2.y);
            a3.x = fmaf(v3.x, n3, a3.x); a3.y = fmaf(v3.y, n3, a3.y);
        } else {
            a0.x += v0.x; a0.y += v0.y; a1.x += v1.x; a1.y += v1.y;
            a2.x += v2.x; a2.y += v2.y; a3.x += v3.x; a3.y += v3.y;
        }
    }
    for (; e < end; e++) {
        int s0 = g_csr_src[e];
        float2 v = *(const float2*)(base + s0 * DIM);
        if (SRCSCALE) {
            float n0 = g_norm_out[s0];
            a0.x = fmaf(v.x, n0, a0.x); a0.y = fmaf(v.y, n0, a0.y);
        } else { a0.x += v.x; a0.y += v.y; }
    }
    float ax = (a0.x + a1.x) + (a2.x + a3.x);
    float ay = (a0.y + a1.y) + (a2.y + a3.y);
    ax *= ni; ay *= ni;
    if (HASB) { ax += bias[l * 2]; ay += bias[l * 2 + 1]; }
    if (RELU) { ax = fmaxf(ax, 0.0f); ay = fmaxf(ay, 0.0f); }
    float2 o; o.x = ax; o.y = ay;
    *(float2*)&hout[node * DIM + l * 2] = o;
}

// ---------------------------------------------------------------------------
// Colpair f32x2 GEMM (R2 loop shape, halved fma count):
//   sW2[cp*KP + k] = (W[k][2cp], W[k][2cp+1])   packed at staging, KP=K+2
//   sXd[r*K + k]   = (x[r][k], x[r][k])          duplicated at staging
//   thread: col-pair cp, RPT=4 strided rows. Zero movs in inner loop.
// ---------------------------------------------------------------------------
template<int K, int M, bool RELU, bool BIAS, bool RSCALE>
__global__ void __launch_bounds__(256, 3)
gemm_kernel(const float* __restrict__ in, const float* __restrict__ W,
            const float* __restrict__ bias, float* __restrict__ out, int n) {
    constexpr int THREADS = 256;
    constexpr int M2 = M / 2;
    constexpr int RPAR = THREADS / M2;
    constexpr int RPT = 4;
    constexpr int RTILE = RPAR * RPT;
    constexpr int KV = K / 4;
    constexpr int KP = K + 2;             // ull stride: conflict-free W loads

    extern __shared__ char smx[];
    ull* sW2 = (ull*)smx;                       // M2*KP
    ull* sXd = (ull*)(smx + (size_t)M2 * KP * 8); // RTILE*K

    const int tid = threadIdx.x;
    for (int idx = tid; idx < K * M2; idx += THREADS) {
        int k = idx / M2, cp = idx % M2;
        float2 w = *(const float2*)&W[k * M + 2 * cp];
        sW2[cp * KP + k] = pk(w.x, w.y);
    }
    __syncthreads();

    int cp = tid % M2;
    int rg = tid / M2;
    const ull* wt = &sW2[cp * KP];

    float2 bv = make_float2(0.f, 0.f);
    if (BIAS) bv = *(const float2*)&bias[2 * cp];

    int ntiles = (n + RTILE - 1) / RTILE;
    for (int t = blockIdx.x; t < ntiles; t += gridDim.x) {
        int row0 = t * RTILE;
        int rows = min(RTILE, n - row0);
        __syncthreads();
        {
            const float4* gin = (const float4*)&in[(size_t)row0 * K];
            int nv = rows * KV;
            for (int idx = tid; idx < nv; idx += THREADS) {
                float4 v = gin[idx];
                ull* d = &sXd[(idx / KV) * K + (idx % KV) * 4];
                d[0] = pk(v.x, v.x); d[1] = pk(v.y, v.y);
                d[2] = pk(v.z, v.z); d[3] = pk(v.w, v.w);
            }
        }
        __syncthreads();
        ull acc[RPT];
        #pragma unroll
        for (int r = 0; r < RPT; r++) acc[r] = 0ULL;
        #pragma unroll 4
        for (int k4 = 0; k4 < KV; k4++) {
            ulonglong2 wa = *(const ulonglong2*)&wt[k4 * 4];
            ulonglong2 wb = *(const ulonglong2*)&wt[k4 * 4 + 2];
            #pragma unroll
            for (int r = 0; r < RPT; r++) {
                int rr = rg + r * RPAR;
                const ull* xp = &sXd[rr * K + k4 * 4];
                ulonglong2 xa = *(const ulonglong2*)xp;
                ulonglong2 xb = *(const ulonglong2*)(xp + 2);
                fma2(acc[r], xa.x, wa.x);
                fma2(acc[r], xa.y, wa.y);
                fma2(acc[r], xb.x, wb.x);
                fma2(acc[r], xb.y, wb.y);
            }
        }
        #pragma unroll
        for (int r = 0; r < RPT; r++) {
            int rr = rg + r * RPAR;
            if (rr < rows) {
                int row = row0 + rr;
                float2 f = upk(acc[r]);
                if (BIAS) { f.x += bv.x; f.y += bv.y; }
                if (RSCALE) {
                    float rs = g_norm_out[row];
                    f.x *= rs; f.y *= rs;
                }
                if (RELU) { f.x = fmaxf(f.x, 0.f); f.y = fmaxf(f.y, 0.f); }
                *(float2*)&out[(size_t)row * M + 2 * cp] = f;
            }
        }
    }
}

// ---------------------------------------------------------------------------
// Fused: agg(h,32) *norm_in +b3, relu -> @W4[32,4] -> *norm_out -> hout (4-dim)
// Warp per node; full 32-dim row lives across lanes, W4 folded via shfl-reduce.
// ---------------------------------------------------------------------------
__global__ void agg32_gemm4(const float* __restrict__ hin,
                            const float* __restrict__ W4,
                            const float* __restrict__ b3,
                            float* __restrict__ hout, int n) {
    int warp = (blockIdx.x * blockDim.x + threadIdx.x) >> 5;
    int lane = threadIdx.x & 31;
    if (warp >= n) return;
    int node = warp;
    float4 w4 = *(const float4*)&W4[lane * 4];
    float bl = b3[lane];
    int beg = g_row_ptr[node], end = g_row_ptr[node + 1];
    const float* base = hin + lane;
    float a0 = 0, a1 = 0, a2 = 0, a3 = 0;
    int e = beg;
    for (; e + 3 < end; e += 4) {
        a0 += base[g_csr_src[e] * 32];
        a1 += base[g_csr_src[e + 1] * 32];
        a2 += base[g_csr_src[e + 2] * 32];
        a3 += base[g_csr_src[e + 3] * 32];
    }
    for (; e < end; e++) a0 += base[g_csr_src[e] * 32];
    float a = fmaxf(fmaf(((a0 + a1) + (a2 + a3)), g_norm_in[node], bl), 0.0f);
    float4 y;
    y.x = a * w4.x; y.y = a * w4.y; y.z = a * w4.z; y.w = a * w4.w;
    #pragma unroll
    for (int o = 16; o; o >>= 1) {
        y.x += __shfl_xor_sync(0xffffffffu, y.x, o);
        y.y += __shfl_xor_sync(0xffffffffu, y.y, o);
        y.z += __shfl_xor_sync(0xffffffffu, y.z, o);
        y.w += __shfl_xor_sync(0xffffffffu, y.w, o);
    }
    if (lane == 0) {
        float s = g_norm_out[node];
        y.x *= s; y.y *= s; y.z *= s; y.w *= s;
        *(float4*)&hout[(size_t)node * 4] = y;
    }
}

// ---------------------------------------------------------------------------
// Final: agg(h,4) * norm_in + b4 -> per-graph sum + count (gids sorted).
// ---------------------------------------------------------------------------
__global__ void agg4_readout(const float* __restrict__ hin,
                             const float* __restrict__ b4,
                             const int* __restrict__ gid, int n) {
    int warp = (blockIdx.x * blockDim.x + threadIdx.x) >> 5;
    int lane = threadIdx.x & 31;
    int node = warp * 8 + (lane >> 2);
    int l = lane & 3;
    float v = 0.f;
    int g = 0;
    bool valid = node < n;
    if (valid) {
        int beg = g_row_ptr[node], end = g_row_ptr[node + 1];
        float a0 = 0, a1 = 0, a2 = 0, a3 = 0;
        int e = beg;
        for (; e + 3 < end; e += 4) {
            a0 += hin[g_csr_src[e] * 4 + l];
            a1 += hin[g_csr_src[e + 1] * 4 + l];
            a2 += hin[g_csr_src[e + 2] * 4 + l];
            a3 += hin[g_csr_src[e + 3] * 4 + l];
        }
        for (; e < end; e++) a0 += hin[g_csr_src[e] * 4 + l];
        v = fmaf(((a0 + a1) + (a2 + a3)), g_norm_in[node], b4[l]);
        g = gid[node];
    }
    unsigned act = __ballot_sync(0xffffffffu, valid);
    if (act == 0xffffffffu) {
        int g0 = __shfl_sync(0xffffffffu, g, 0);
        if (__all_sync(0xffffffffu, g == g0)) {
            v += __shfl_xor_sync(0xffffffffu, v, 4);
            v += __shfl_xor_sync(0xffffffffu, v, 8);
            v += __shfl_xor_sync(0xffffffffu, v, 16);
            if (lane < 4) atomicAdd(&g_gsum[g0 * 4 + lane], v);
            if (lane == 0) atomicAdd(&g_gcnt[g0], 8);
            return;
        }
    }
    if (valid) {
        atomicAdd(&g_gsum[g * 4 + l], v);
        if (l == 0) atomicAdd(&g_gcnt[g], 1);
    }
}

__global__ void graph_mean_kernel(float* __restrict__ out, int g) {
    int i = blockIdx.x * blockDim.x + threadIdx.x;
    if (i < g * 4) {
        float c = fmaxf((float)g_gcnt[i >> 2], 1.0f);
        out[i] = g_gsum[i] / c;
    }
}

// ---------------------------------------------------------------------------
extern "C" void kernel_launch(void* const* d_in, const int* in_sizes, int n_in,
                              void* d_out, int out_size) {
    const float* x  = (const float*)d_in[0];
    const float* W1 = (const float*)d_in[1];
    const float* b1 = (const float*)d_in[2];
    const float* W2 = (const float*)d_in[3];
    const float* b2 = (const float*)d_in[4];
    const float* W3 = (const float*)d_in[5];
    const float* b3 = (const float*)d_in[6];
    const float* W4 = (const float*)d_in[7];
    const float* b4 = (const float*)d_in[8];
    const int* src = (const int*)d_in[9];
    const int* dst = (const int*)d_in[10];
    const int* gid = (const int*)d_in[11];
    float* out = (float*)d_out;

    int n = in_sizes[0] / 64;   // nodes
    int e = in_sizes[9];        // edges
    int g = out_size / 4;       // graphs

    float *h0, *h1;
    cudaGetSymbolAddress((void**)&h0, g_h0);
    cudaGetSymbolAddress((void**)&h1, g_h1);

    const int T = 256;
    auto blocks = [](int work, int t) { return (work + t - 1) / t; };
    auto warp_grid = [&](int nodes_per_warp) {
        int warps = (n + nodes_per_warp - 1) / nodes_per_warp;
        return (warps * 32 + T - 1) / T;
    };

    // GEMM dynamic smem: sW2 = M2*(K+2)*8, sXd = RTILE*K*8
    // gemm1 (64->128): M2=64, RTILE=16 -> 33792 + 8192  = 41984
    // gemm2 (128->64): M2=32, RTILE=32 -> 33280 + 32768 = 66048
    // gemm3 (64->32):  M2=16, RTILE=64 ->  8448 + 32768 = 41216
    const int SM1 = 64 * 66 * 8 + 16 * 64 * 8;
    const int SM2 = 32 * 130 * 8 + 32 * 128 * 8;
    const int SM3 = 16 * 66 * 8 + 64 * 64 * 8;
    cudaFuncSetAttribute((const void*)gemm_kernel<64, 128, true, true, false>,
                         cudaFuncAttributeMaxDynamicSharedMemorySize, SM1);
    cudaFuncSetAttribute((const void*)gemm_kernel<128, 64, false, false, true>,
                         cudaFuncAttributeMaxDynamicSharedMemorySize, SM2);
    cudaFuncSetAttribute((const void*)gemm_kernel<64, 32, false, false, true>,
                         cudaFuncAttributeMaxDynamicSharedMemorySize, SM3);

    // Graph preprocessing
    int nb = (n + 1023) / 1024;
    zero_kernel<<<blocks(n, T), T>>>(n, g);
    degree_kernel<<<blocks(e, T), T>>>(src, dst, e);
    scan_pass1<<<nb, 256>>>(n);
    scan_pass2<<<1, 128>>>(nb, n);
    scan_pass3<<<nb, 256>>>(n);
    csr_fill_kernel<<<blocks(e, T), T>>>(src, dst, e);

    const int GG = 444;  // 148 SMs * 3

    // Layer 1: agg(x * norm_out) -> *norm_in -> @W1 + b1, relu
    agg_kernel<64, false, false, true><<<warp_grid(1), T>>>(x, h1, nullptr, n);
    gemm_kernel<64, 128, true, true, false><<<GG, 256, SM1>>>(h1, W1, b1, h0, n);

    // Layer 2: (h @ W2) * norm_out -> agg -> *norm_in + b2, relu
    gemm_kernel<128, 64, false, false, true><<<GG, 256, SM2>>>(h0, W2, nullptr, h1, n);
    agg_kernel<64, true, true, false><<<warp_grid(1), T>>>(h1, h0, b2, n);

    // Layer 3: (h @ W3) * norm_out
    gemm_kernel<64, 32, false, false, true><<<GG, 256, SM3>>>(h0, W3, nullptr, h1, n);

    // Layer 3 agg + layer 4 gemm fused: agg32 -> +b3, relu -> @W4 -> *norm_out
    agg32_gemm4<<<warp_grid(1), T>>>(h1, W4, b3, h0, n);

    // Layer 4 agg + readout
    agg4_readout<<<warp_grid(8), T>>>(h0, b4, gid, n);
    graph_mean_kernel<<<blocks(g * 4, T), T>>>(out, g);
}